// round 11
// baseline (speedup 1.0000x reference)
#include <cuda_runtime.h>
#include <cuda_bf16.h>
#include <math.h>
#include <stdint.h>

// Problem constants
#define BATCH 32
#define TSTEPS 300
#define CIN   2312        // 34*34*2
#define O1    512
#define O2    512
#define O3    10
#define O3PAD 128
#define MROWS (BATCH*TSTEPS)   // 9600
#define KC    248         // Eigen accumulation panel (bit-exactness anchor)
#define SC    124         // smem staging sub-panel (2 per KC panel)
#define NSMAX 19
#define CW1   73          // mask words per row, layer1
#define CW2   16          // mask words per row, layers 2/3

// ---------------- static device scratch ----------------
__device__ float g_z  [ (size_t)BATCH*TSTEPS*O1  ];
__device__ float g_W1t[ (size_t)CIN*O1 ];
__device__ float g_W2t[ (size_t)O1*O2 ];
__device__ float g_W3t[ (size_t)O2*O3PAD ];
__device__ unsigned g_mask1[(size_t)MROWS*CW1];
__device__ unsigned g_mask2[(size_t)MROWS*CW2];
__device__ unsigned short g_idx1[(size_t)MROWS*CIN];
__device__ unsigned short g_idx2[(size_t)MROWS*O1];
__device__ int g_cntS[(size_t)MROWS*NSMAX];
__device__ unsigned long long g_cnt[3];

// ---------------- cp.async helpers ----------------
__device__ __forceinline__ void cp_async16(uint32_t saddr, const void* gaddr) {
    asm volatile("cp.async.cg.shared.global [%0], [%1], 16;" :: "r"(saddr), "l"(gaddr));
}
__device__ __forceinline__ void cp_commit() {
    asm volatile("cp.async.commit_group;");
}
template <int N> __device__ __forceinline__ void cp_wait() {
    asm volatile("cp.async.wait_group %0;" :: "n"(N));
}
__device__ __forceinline__ uint32_t smem_u32(const void* p) {
    return (uint32_t)__cvta_generic_to_shared(p);
}

// ---------------- init ----------------
__global__ void init_kernel() {
    int tid = blockIdx.x * blockDim.x + threadIdx.x;
    if (tid < 3) g_cnt[tid] = 0ull;
    for (int i = tid; i < O2 * O3PAD; i += gridDim.x * blockDim.x)
        g_W3t[i] = 0.0f;
}

// ---------------- transpose spikes -> bitmask [B,T,CW1] --------------------
__global__ void transpose_mask_kernel(const float* __restrict__ in) {
    __shared__ float tile[32][33];
    int b  = blockIdx.z;
    int t0 = blockIdx.x * 32;
    int cw = blockIdx.y;
    int c0 = cw * 32;
    int tx = threadIdx.x, ty = threadIdx.y;   // (32,8)
    const float* inb = in + (size_t)b * CIN * TSTEPS;
    int t = t0 + tx;
    #pragma unroll
    for (int j = 0; j < 32; j += 8) {
        int c = c0 + ty + j;
        float v = 0.0f;
        if (t < TSTEPS && c < CIN) v = inb[(size_t)c * TSTEPS + t];
        tile[ty + j][tx] = v;
    }
    __syncthreads();
    #pragma unroll
    for (int j = 0; j < 32; j += 8) {
        int t2 = t0 + ty + j;
        float v = tile[tx][ty + j];
        unsigned word = __ballot_sync(0xffffffffu, v != 0.0f);
        if (tx == 0 && t2 < TSTEPS)
            g_mask1[(size_t)(b * TSTEPS + t2) * CW1 + cw] = word;
    }
}

// ---------------- fused norm + scale + transpose ---------------------------
// Phase A: NEON 4-lane norms for a 32-o slab (bit-identical order).
// Phase B: Wt[c][o] = fdiv(fmul(g,v), norm) via 32x32 tile transpose, c-loop.
__global__ __launch_bounds__(256)
void normscale_kernel(const float* __restrict__ v, const float* __restrict__ g,
                      float* __restrict__ Wt, int O, int C, int ldw) {
    __shared__ float nrm_s[32];
    __shared__ float tile[32][33];
    const int o0 = blockIdx.x * 32;
    const int tid = threadIdx.y * 32 + threadIdx.x;

    if (tid < 128) {
        int j = tid & 3;
        int r = tid >> 2;                  // 0..31
        int o = o0 + r;
        int oc = (o < O) ? o : (O - 1);    // clamp loads, keep groups converged
        const float* vr = v + (size_t)oc * C;
        float s = 0.0f;
        for (int c = j; c < C; c += 4)
            s = __fadd_rn(s, __fmul_rn(vr[c], vr[c]));
        unsigned gm = 0xFu << ((((unsigned)tid & 31u) >> 2) << 2);
        float u  = __shfl_down_sync(gm, s, 1, 4);
        float a  = __fadd_rn(s, u);
        float b2 = __shfl_down_sync(gm, a, 2, 4);
        if (j == 0) nrm_s[r] = sqrtf(__fadd_rn(a, b2));
    }
    __syncthreads();

    int tx = threadIdx.x, ty = threadIdx.y;   // (32,8)
    for (int c0 = 0; c0 < C; c0 += 32) {
        #pragma unroll
        for (int jj = 0; jj < 32; jj += 8) {
            int o = o0 + ty + jj, c = c0 + tx;
            if (o < O && c < C)
                tile[ty + jj][tx] = __fdiv_rn(__fmul_rn(g[o], v[(size_t)o * C + c]),
                                              nrm_s[ty + jj]);
        }
        __syncthreads();
        #pragma unroll
        for (int jj = 0; jj < 32; jj += 8) {
            int c = c0 + ty + jj, o = o0 + tx;
            if (o < O && c < C)
                Wt[(size_t)c * ldw + o] = tile[tx][ty + jj];
        }
        __syncthreads();
    }
}

// ---------------- build idx lists + subchunk counts from bitmasks ----------
__global__ void buildm_kernel(const unsigned* __restrict__ mask,
                              unsigned short* __restrict__ idx,
                              int* __restrict__ cntS, int NW, int K, int NS) {
    __shared__ unsigned sw[8][80];
    int warp = threadIdx.x >> 5, lane = threadIdx.x & 31;
    int row = blockIdx.x * 8 + warp;
    const unsigned* mr = mask + (size_t)row * NW;
    for (int w = lane; w < NW; w += 32) sw[warp][w] = mr[w];
    __syncwarp();

    unsigned short* ir = idx + (size_t)row * K;
    int pos = 0;
    int ngroups = (NW + 31) >> 5;
    for (int g = 0; g < ngroups; g++) {
        int w = g * 32 + lane;
        unsigned word = (w < NW) ? sw[warp][w] : 0u;
        int pc = __popc(word);
        int scan = pc;
        #pragma unroll
        for (int off = 1; off < 32; off <<= 1) {
            int n = __shfl_up_sync(0xffffffffu, scan, off);
            if (lane >= off) scan += n;
        }
        int base = pos + (scan - pc);
        unsigned ww = word;
        int r = 0;
        while (ww) {
            int bit = __ffs(ww) - 1;
            ir[base + r] = (unsigned short)(32 * w + bit);
            r++;
            ww &= ww - 1u;
        }
        pos += __shfl_sync(0xffffffffu, scan, 31);
    }
    if (lane < NS) {
        int start = lane * SC;
        int end = start + SC; if (end > K) end = K;
        int wlo = start >> 5, whi = (end - 1) >> 5;
        int cnt = 0;
        for (int w = wlo; w <= whi; w++) {
            unsigned m = sw[warp][w];
            int cbase = w << 5;
            if (cbase < start) m &= ~((1u << (start - cbase)) - 1u);
            int rem = end - cbase;
            if (rem < 32) m &= (1u << rem) - 1u;
            cnt += __popc(m);
        }
        cntS[row * NSMAX + lane] = cnt;
    }
}

// ---------------- sparse accumulate: 1024 thr, cp.async double buffer ------
// Bit-exact: per KC panel an ascending-c fadd chain (2 SC stages, fold after
// odd/final stage), panels folded by fadd.  Warp covers 128 cols.
#define OT  128
#define RPB 128
#define RPW 4       // 32 warps x 4 rows

extern __shared__ float Ws[];   // 2 x [SC][OT] = 126976 bytes

__global__ __launch_bounds__(1024)
void spmm_kernel(const unsigned short* __restrict__ idx, const int* __restrict__ cntS,
                 const float* __restrict__ W, float* __restrict__ Z,
                 int K, int NS, int ldw, int ldc) {
    const int tid  = threadIdx.x;
    const int lane = tid & 31;
    const int warp = tid >> 5;
    const int row0 = blockIdx.x * RPB + warp * RPW;
    const int o0   = blockIdx.y * OT;
    const int ocol = lane * 4;
    const uint32_t sbase = smem_u32(Ws);

    float4 acc[RPW], accP[RPW];
    int pos[RPW];
    #pragma unroll
    for (int j = 0; j < RPW; j++) {
        acc[j] = make_float4(0.f,0.f,0.f,0.f);
        accP[j] = make_float4(0.f,0.f,0.f,0.f);
        pos[j] = 0;
    }

    {
        int slen = (K < SC) ? K : SC;
        for (int i4 = tid; i4 < slen * (OT / 4); i4 += 1024) {
            int r = i4 >> 5, c4 = (i4 & 31) << 2;
            cp_async16(sbase + (uint32_t)(r * OT + c4) * 4u,
                       W + (size_t)r * ldw + o0 + c4);
        }
        cp_commit();
    }

    int buf = 0;
    for (int s = 0; s < NS; s++) {
        if (s + 1 < NS) {
            int ss = (s + 1) * SC;
            int slen = K - ss; if (slen > SC) slen = SC;
            uint32_t bofs = (uint32_t)((buf ^ 1) * SC * OT) * 4u;
            for (int i4 = tid; i4 < slen * (OT / 4); i4 += 1024) {
                int r = i4 >> 5, c4 = (i4 & 31) << 2;
                cp_async16(sbase + bofs + (uint32_t)(r * OT + c4) * 4u,
                           W + (size_t)(ss + r) * ldw + o0 + c4);
            }
            cp_commit();
            cp_wait<1>();
        } else {
            cp_wait<0>();
        }
        __syncthreads();

        const int ss = s * SC;
        const float* Wb = Ws + buf * SC * OT;
        #pragma unroll
        for (int j = 0; j < RPW; j++) {
            const int row = row0 + j;
            const int cnt = cntS[row * NSMAX + s];
            const unsigned short* ip = idx + (size_t)row * K + pos[j];
            float4 a = accP[j];
            for (int i = 0; i < cnt; i++) {
                int c = ip[i];
                float4 wv = *(const float4*)&Wb[(c - ss) * OT + ocol];
                a.x = __fadd_rn(a.x, wv.x);
                a.y = __fadd_rn(a.y, wv.y);
                a.z = __fadd_rn(a.z, wv.z);
                a.w = __fadd_rn(a.w, wv.w);
            }
            accP[j] = a;
            pos[j] += cnt;
        }
        __syncthreads();

        if ((s & 1) == 1 || s == NS - 1) {
            #pragma unroll
            for (int j = 0; j < RPW; j++) {
                acc[j].x = __fadd_rn(acc[j].x, accP[j].x);
                acc[j].y = __fadd_rn(acc[j].y, accP[j].y);
                acc[j].z = __fadd_rn(acc[j].z, accP[j].z);
                acc[j].w = __fadd_rn(acc[j].w, accP[j].w);
                accP[j] = make_float4(0.f,0.f,0.f,0.f);
            }
        }
        buf ^= 1;
    }
    #pragma unroll
    for (int j = 0; j < RPW; j++)
        *(float4*)(Z + (size_t)(row0 + j) * ldc + o0 + ocol) = acc[j];
}

// ---------------- LIF scan, 512-wide: emits next-layer bitmask (U=10) ------
__global__ void scan512_kernel(const float* __restrict__ z, unsigned* __restrict__ maskN,
                               const int* __restrict__ delay, unsigned long long* cnt) {
    int tid = blockIdx.x * blockDim.x + threadIdx.x;  // 16384
    int o = tid & 511;
    int b = tid >> 9;
    int lane = tid & 31;
    int d = delay[o];
    const float* zp = z + (size_t)b * TSTEPS * 512 + o;
    unsigned* mw = maskN + (size_t)b * TSTEPS * CW2 + (o >> 5);
    float cur = 0.0f, vol = 0.0f;
    unsigned hist = 0u;
    int c = 0;
    for (int t = 0; t < TSTEPS; t += 10) {
        float za[10];
        #pragma unroll
        for (int u = 0; u < 10; u++) za[u] = zp[(size_t)(t + u) * 512];
        #pragma unroll
        for (int u = 0; u < 10; u++) {
            cur = fmaf(cur, 0.75f, za[u]);
            float v = fmaf(vol, 0.97f, cur);
            int s = (__fadd_rn(v, -1.25f) >= 0.0f);
            vol = s ? 0.0f : v;
            hist = (hist << 1) | (unsigned)s;
            int tt = t + u;
            int sv = (tt >= d) ? (int)((hist >> d) & 1u) : 0;
            unsigned word = __ballot_sync(0xffffffffu, sv);
            if (lane == 0) mw[(size_t)tt * CW2] = word;
            c += sv;
        }
    }
    atomicAdd(cnt, (unsigned long long)c);
}

// ---------------- LIF scan, output layer (z ld = O3PAD, U=10) --------------
__global__ void scan_out_kernel(const float* __restrict__ z, float* __restrict__ out,
                                const int* __restrict__ delay, unsigned long long* cnt) {
    int tid = blockIdx.x * blockDim.x + threadIdx.x;
    if (tid >= BATCH * O3) return;
    int o = tid % O3;
    int b = tid / O3;
    int d = delay[o];
    const float* zp = z + (size_t)b * TSTEPS * O3PAD + o;
    float* op = out + (size_t)b * O3 * TSTEPS + (size_t)o * TSTEPS;
    float cur = 0.0f, vol = 0.0f;
    unsigned hist = 0u;
    int c = 0;
    for (int t = 0; t < TSTEPS; t += 10) {
        float za[10];
        #pragma unroll
        for (int u = 0; u < 10; u++) za[u] = zp[(size_t)(t + u) * O3PAD];
        #pragma unroll
        for (int u = 0; u < 10; u++) {
            cur = fmaf(cur, 0.75f, za[u]);
            float v = fmaf(vol, 0.97f, cur);
            int s = (__fadd_rn(v, -1.25f) >= 0.0f);
            vol = s ? 0.0f : v;
            hist = (hist << 1) | (unsigned)s;
            int tt = t + u;
            int sv = (tt >= d) ? (int)((hist >> d) & 1u) : 0;
            op[tt] = (float)sv;
            c += sv;
        }
    }
    atomicAdd(cnt, (unsigned long long)c);
}

// ---------------- finalize counts ----------------
__global__ void finalize_kernel(float* out) {
    if (threadIdx.x == 0) {
        out[96000] = __fdiv_rn((float)g_cnt[0], 4915200.0f);
        out[96001] = __fdiv_rn((float)g_cnt[1], 4915200.0f);
        out[96002] = __fdiv_rn((float)g_cnt[2], 96000.0f);
    }
}

// ---------------- launch ----------------
extern "C" void kernel_launch(void* const* d_in, const int* in_sizes, int n_in,
                              void* d_out, int out_size) {
    const float* spike = (const float*)d_in[0];
    const float* v1 = (const float*)d_in[1];
    const float* g1 = (const float*)d_in[2];
    const float* v2 = (const float*)d_in[3];
    const float* g2 = (const float*)d_in[4];
    const float* v3 = (const float*)d_in[5];
    const float* g3 = (const float*)d_in[6];
    const int*   d1 = (const int*)d_in[7];
    const int*   d2 = (const int*)d_in[8];
    const int*   d3 = (const int*)d_in[9];
    float* out = (float*)d_out;

    float *z, *W1t, *W2t, *W3t;
    unsigned *mask1, *mask2;
    unsigned short *idx1, *idx2;
    int* cntS;
    unsigned long long* cnt;
    cudaGetSymbolAddress((void**)&z,   g_z);
    cudaGetSymbolAddress((void**)&W1t, g_W1t);
    cudaGetSymbolAddress((void**)&W2t, g_W2t);
    cudaGetSymbolAddress((void**)&W3t, g_W3t);
    cudaGetSymbolAddress((void**)&mask1, g_mask1);
    cudaGetSymbolAddress((void**)&mask2, g_mask2);
    cudaGetSymbolAddress((void**)&idx1, g_idx1);
    cudaGetSymbolAddress((void**)&idx2, g_idx2);
    cudaGetSymbolAddress((void**)&cntS, g_cntS);
    cudaGetSymbolAddress((void**)&cnt, g_cnt);

    static int smem_set = 0;
    if (!smem_set) {
        cudaFuncSetAttribute(spmm_kernel, cudaFuncAttributeMaxDynamicSharedMemorySize,
                             2 * SC * OT * (int)sizeof(float));
        smem_set = 1;
    }
    const int SPMM_SMEM = 2 * SC * OT * (int)sizeof(float);  // 126976

    // ---- layer 1 (launch order puts spmm1 in the profiled slot #4) ----
    {
        dim3 grid((TSTEPS + 31) / 32, CW1, BATCH);
        transpose_mask_kernel<<<grid, dim3(32, 8)>>>(spike);                       // 1
    }
    buildm_kernel<<<MROWS / 8, 256>>>(mask1, idx1, cntS, CW1, CIN, 19);            // 2
    normscale_kernel<<<O1 / 32, dim3(32, 8)>>>(v1, g1, W1t, O1, CIN, O1);          // 3
    spmm_kernel<<<dim3(MROWS / RPB, O1 / OT), 1024, SPMM_SMEM>>>(idx1, cntS, W1t, z, CIN, 19, O1, O1);  // 4
    init_kernel<<<64, 256>>>();                                                    // 5
    scan512_kernel<<<(BATCH * O1) / 256, 256>>>(z, mask2, d1, cnt + 0);            // 6

    // ---- layer 2 ----
    normscale_kernel<<<O2 / 32, dim3(32, 8)>>>(v2, g2, W2t, O2, O1, O2);
    buildm_kernel<<<MROWS / 8, 256>>>(mask2, idx2, cntS, CW2, O1, 5);
    spmm_kernel<<<dim3(MROWS / RPB, O2 / OT), 1024, SPMM_SMEM>>>(idx2, cntS, W2t, z, O1, 5, O2, O2);
    scan512_kernel<<<(BATCH * O2) / 256, 256>>>(z, mask2, d2, cnt + 1);

    // ---- layer 3 (N padded to 128) ----
    normscale_kernel<<<1, dim3(32, 8)>>>(v3, g3, W3t, O3, O2, O3PAD);
    buildm_kernel<<<MROWS / 8, 256>>>(mask2, idx2, cntS, CW2, O2, 5);
    spmm_kernel<<<dim3(MROWS / RPB, 1), 1024, SPMM_SMEM>>>(idx2, cntS, W3t, z, O2, 5, O3PAD, O3PAD);
    scan_out_kernel<<<2, 256>>>(z, out, d3, cnt + 2);

    finalize_kernel<<<1, 32>>>(out);
}

// round 12
// speedup vs baseline: 1.0879x; 1.0879x over previous
#include <cuda_runtime.h>
#include <cuda_bf16.h>
#include <math.h>
#include <stdint.h>

// Problem constants
#define BATCH 32
#define TSTEPS 300
#define CIN   2312        // 34*34*2
#define O1    512
#define O2    512
#define O3    10
#define O3PAD 128
#define MROWS (BATCH*TSTEPS)   // 9600
#define KC    248         // Eigen accumulation panel (bit-exactness anchor)
#define SC    124         // smem staging sub-panel (2 per KC panel)
#define NSMAX 19
#define CW1   73          // mask words per row, layer1
#define CW2   16          // mask words per row, layers 2/3

// ---------------- static device scratch ----------------
__device__ float g_z  [ (size_t)BATCH*TSTEPS*O1  ];
__device__ float g_W1t[ (size_t)CIN*O1 ];
__device__ float g_W2t[ (size_t)O1*O2 ];
__device__ float g_W3t[ (size_t)O2*O3PAD ];
__device__ float g_norm[512];
__device__ unsigned g_mask1[(size_t)MROWS*CW1];
__device__ unsigned g_mask2[(size_t)MROWS*CW2];
__device__ unsigned short g_idx1[(size_t)MROWS*CIN];
__device__ unsigned short g_idx2[(size_t)MROWS*O1];
__device__ int g_cntS[(size_t)MROWS*NSMAX];
__device__ unsigned long long g_cnt[3];

// ---------------- cp.async helpers ----------------
__device__ __forceinline__ void cp_async16(uint32_t saddr, const void* gaddr) {
    asm volatile("cp.async.cg.shared.global [%0], [%1], 16;" :: "r"(saddr), "l"(gaddr));
}
__device__ __forceinline__ void cp_commit() {
    asm volatile("cp.async.commit_group;");
}
template <int N> __device__ __forceinline__ void cp_wait() {
    asm volatile("cp.async.wait_group %0;" :: "n"(N));
}
__device__ __forceinline__ uint32_t smem_u32(const void* p) {
    return (uint32_t)__cvta_generic_to_shared(p);
}

// ---------------- init ----------------
__global__ void init_kernel() {
    int tid = blockIdx.x * blockDim.x + threadIdx.x;
    if (tid < 3) g_cnt[tid] = 0ull;
    for (int i = tid; i < O2 * O3PAD; i += gridDim.x * blockDim.x)
        g_W3t[i] = 0.0f;
}

// ---------------- transpose spikes -> bitmask [B,T,CW1] --------------------
__global__ void transpose_mask_kernel(const float* __restrict__ in) {
    __shared__ float tile[32][33];
    int b  = blockIdx.z;
    int t0 = blockIdx.x * 32;
    int cw = blockIdx.y;
    int c0 = cw * 32;
    int tx = threadIdx.x, ty = threadIdx.y;   // (32,8)
    const float* inb = in + (size_t)b * CIN * TSTEPS;
    int t = t0 + tx;
    #pragma unroll
    for (int j = 0; j < 32; j += 8) {
        int c = c0 + ty + j;
        float v = 0.0f;
        if (t < TSTEPS && c < CIN) v = inb[(size_t)c * TSTEPS + t];
        tile[ty + j][tx] = v;
    }
    __syncthreads();
    #pragma unroll
    for (int j = 0; j < 32; j += 8) {
        int t2 = t0 + ty + j;
        float v = tile[tx][ty + j];
        unsigned word = __ballot_sync(0xffffffffu, v != 0.0f);
        if (tx == 0 && t2 < TSTEPS)
            g_mask1[(size_t)(b * TSTEPS + t2) * CW1 + cw] = word;
    }
}

// ---------------- norm: NEON 4-lane reduce, 4 threads per row -------------
__global__ void norm4_kernel(const float* __restrict__ v, float* __restrict__ nrm,
                             int O, int C) {
    int t = blockIdx.x * blockDim.x + threadIdx.x;
    int j = t & 3;
    int o = t >> 2;
    int oc = (o < O) ? o : (O - 1);
    const float* vr = v + (size_t)oc * C;
    float s = 0.0f;
    for (int c = j; c < C; c += 4)
        s = __fadd_rn(s, __fmul_rn(vr[c], vr[c]));
    unsigned gm = 0xFu << ((((unsigned)t & 31u) >> 2) << 2);
    float u  = __shfl_down_sync(gm, s, 1, 4);
    float a  = __fadd_rn(s, u);
    float b2 = __shfl_down_sync(gm, a, 2, 4);
    if (j == 0 && o < O) nrm[o] = sqrtf(__fadd_rn(a, b2));
}

// ---------------- scale + transpose ----------------
__global__ void scale_kernel(const float* __restrict__ v, const float* __restrict__ g,
                             const float* __restrict__ nrm, float* __restrict__ Wt,
                             int O, int C, int ldw) {
    __shared__ float tile[32][33];
    int c0 = blockIdx.x * 32, o0 = blockIdx.y * 32;
    int tx = threadIdx.x, ty = threadIdx.y;
    #pragma unroll
    for (int jj = 0; jj < 32; jj += 8) {
        int o = o0 + ty + jj, c = c0 + tx;
        if (o < O && c < C)
            tile[ty + jj][tx] = __fdiv_rn(__fmul_rn(g[o], v[(size_t)o * C + c]), nrm[o]);
    }
    __syncthreads();
    #pragma unroll
    for (int jj = 0; jj < 32; jj += 8) {
        int c = c0 + ty + jj, o = o0 + tx;
        if (o < O && c < C)
            Wt[(size_t)c * ldw + o] = tile[tx][ty + jj];
    }
}

// ---------------- build idx (byte offsets) + subchunk counts ---------------
// Emits per-nz u16 byte offset (c - sub*SC) * OT * 4 within its SC subchunk
// (walk order unchanged -> spmm accumulation order bit-identical).
#define OTB 512     // OT * 4 bytes
__global__ void buildm_kernel(const unsigned* __restrict__ mask,
                              unsigned short* __restrict__ idx,
                              int* __restrict__ cntS, int NW, int K, int NS) {
    __shared__ unsigned sw[8][80];
    int warp = threadIdx.x >> 5, lane = threadIdx.x & 31;
    int row = blockIdx.x * 8 + warp;
    const unsigned* mr = mask + (size_t)row * NW;
    for (int w = lane; w < NW; w += 32) sw[warp][w] = mr[w];
    __syncwarp();

    unsigned short* ir = idx + (size_t)row * K;
    int pos = 0;
    int ngroups = (NW + 31) >> 5;
    for (int g = 0; g < ngroups; g++) {
        int w = g * 32 + lane;
        unsigned word = (w < NW) ? sw[warp][w] : 0u;
        int pc = __popc(word);
        int scan = pc;
        #pragma unroll
        for (int off = 1; off < 32; off <<= 1) {
            int n = __shfl_up_sync(0xffffffffu, scan, off);
            if (lane >= off) scan += n;
        }
        int base = pos + (scan - pc);
        unsigned ww = word;
        int r = 0;
        while (ww) {
            int bit = __ffs(ww) - 1;
            int c = 32 * w + bit;
            int sub = c / SC;
            ir[base + r] = (unsigned short)((c - sub * SC) * OTB);
            r++;
            ww &= ww - 1u;
        }
        pos += __shfl_sync(0xffffffffu, scan, 31);
    }
    if (lane < NS) {
        int start = lane * SC;
        int end = start + SC; if (end > K) end = K;
        int wlo = start >> 5, whi = (end - 1) >> 5;
        int cnt = 0;
        for (int w = wlo; w <= whi; w++) {
            unsigned m = sw[warp][w];
            int cbase = w << 5;
            if (cbase < start) m &= ~((1u << (start - cbase)) - 1u);
            int rem = end - cbase;
            if (rem < 32) m &= (1u << rem) - 1u;
            cnt += __popc(m);
        }
        cntS[row * NSMAX + lane] = cnt;
    }
}

// ---------------- sparse accumulate: 1024 thr, cp.async double buffer ------
// Bit-exact: per KC panel an ascending-c fadd chain (2 SC stages, fold after
// odd/final stage), panels folded by fadd.  Warp covers 128 cols; inner loop
// unrolled x4 with hoisted LDS.128s, adds applied in ascending order.
#define OT  128
#define RPB 128
#define RPW 4       // 32 warps x 4 rows

extern __shared__ float Ws[];   // 2 x [SC][OT] = 126976 bytes

__global__ __launch_bounds__(1024)
void spmm_kernel(const unsigned short* __restrict__ idx, const int* __restrict__ cntS,
                 const float* __restrict__ W, float* __restrict__ Z,
                 int K, int NS, int ldw, int ldc) {
    const int tid  = threadIdx.x;
    const int lane = tid & 31;
    const int warp = tid >> 5;
    const int row0 = blockIdx.x * RPB + warp * RPW;
    const int o0   = blockIdx.y * OT;
    const int ocol = lane * 4;
    const uint32_t sbase = smem_u32(Ws);

    float4 acc[RPW], accP[RPW];
    int pos[RPW];
    #pragma unroll
    for (int j = 0; j < RPW; j++) {
        acc[j] = make_float4(0.f,0.f,0.f,0.f);
        accP[j] = make_float4(0.f,0.f,0.f,0.f);
        pos[j] = 0;
    }

    {
        int slen = (K < SC) ? K : SC;
        for (int i4 = tid; i4 < slen * (OT / 4); i4 += 1024) {
            int r = i4 >> 5, c4 = (i4 & 31) << 2;
            cp_async16(sbase + (uint32_t)(r * OT + c4) * 4u,
                       W + (size_t)r * ldw + o0 + c4);
        }
        cp_commit();
    }

    int buf = 0;
    for (int s = 0; s < NS; s++) {
        if (s + 1 < NS) {
            int ss = (s + 1) * SC;
            int slen = K - ss; if (slen > SC) slen = SC;
            uint32_t bofs = (uint32_t)((buf ^ 1) * SC * OT) * 4u;
            for (int i4 = tid; i4 < slen * (OT / 4); i4 += 1024) {
                int r = i4 >> 5, c4 = (i4 & 31) << 2;
                cp_async16(sbase + bofs + (uint32_t)(r * OT + c4) * 4u,
                           W + (size_t)(ss + r) * ldw + o0 + c4);
            }
            cp_commit();
            cp_wait<1>();
        } else {
            cp_wait<0>();
        }
        __syncthreads();

        const char* wb = (const char*)(Ws + buf * SC * OT) + ocol * 4;
        #pragma unroll
        for (int j = 0; j < RPW; j++) {
            const int row = row0 + j;
            const int cnt = cntS[row * NSMAX + s];
            const unsigned short* ip = idx + (size_t)row * K + pos[j];
            float4 a = accP[j];
            int i = 0;
            for (; i + 4 <= cnt; i += 4) {
                float4 w0 = *(const float4*)(wb + ip[i + 0]);
                float4 w1 = *(const float4*)(wb + ip[i + 1]);
                float4 w2 = *(const float4*)(wb + ip[i + 2]);
                float4 w3 = *(const float4*)(wb + ip[i + 3]);
                a.x = __fadd_rn(a.x, w0.x); a.y = __fadd_rn(a.y, w0.y);
                a.z = __fadd_rn(a.z, w0.z); a.w = __fadd_rn(a.w, w0.w);
                a.x = __fadd_rn(a.x, w1.x); a.y = __fadd_rn(a.y, w1.y);
                a.z = __fadd_rn(a.z, w1.z); a.w = __fadd_rn(a.w, w1.w);
                a.x = __fadd_rn(a.x, w2.x); a.y = __fadd_rn(a.y, w2.y);
                a.z = __fadd_rn(a.z, w2.z); a.w = __fadd_rn(a.w, w2.w);
                a.x = __fadd_rn(a.x, w3.x); a.y = __fadd_rn(a.y, w3.y);
                a.z = __fadd_rn(a.z, w3.z); a.w = __fadd_rn(a.w, w3.w);
            }
            for (; i < cnt; i++) {
                float4 wv = *(const float4*)(wb + ip[i]);
                a.x = __fadd_rn(a.x, wv.x); a.y = __fadd_rn(a.y, wv.y);
                a.z = __fadd_rn(a.z, wv.z); a.w = __fadd_rn(a.w, wv.w);
            }
            accP[j] = a;
            pos[j] += cnt;
        }
        __syncthreads();

        if ((s & 1) == 1 || s == NS - 1) {
            #pragma unroll
            for (int j = 0; j < RPW; j++) {
                acc[j].x = __fadd_rn(acc[j].x, accP[j].x);
                acc[j].y = __fadd_rn(acc[j].y, accP[j].y);
                acc[j].z = __fadd_rn(acc[j].z, accP[j].z);
                acc[j].w = __fadd_rn(acc[j].w, accP[j].w);
                accP[j] = make_float4(0.f,0.f,0.f,0.f);
            }
        }
        buf ^= 1;
    }
    #pragma unroll
    for (int j = 0; j < RPW; j++)
        *(float4*)(Z + (size_t)(row0 + j) * ldc + o0 + ocol) = acc[j];
}

// ---------------- LIF scan, 512-wide: emits next-layer bitmask (U=10) ------
__global__ void scan512_kernel(const float* __restrict__ z, unsigned* __restrict__ maskN,
                               const int* __restrict__ delay, unsigned long long* cnt) {
    int tid = blockIdx.x * blockDim.x + threadIdx.x;  // 16384
    int o = tid & 511;
    int b = tid >> 9;
    int lane = tid & 31;
    int d = delay[o];
    const float* zp = z + (size_t)b * TSTEPS * 512 + o;
    unsigned* mw = maskN + (size_t)b * TSTEPS * CW2 + (o >> 5);
    float cur = 0.0f, vol = 0.0f;
    unsigned hist = 0u;
    int c = 0;
    for (int t = 0; t < TSTEPS; t += 10) {
        float za[10];
        #pragma unroll
        for (int u = 0; u < 10; u++) za[u] = zp[(size_t)(t + u) * 512];
        #pragma unroll
        for (int u = 0; u < 10; u++) {
            cur = fmaf(cur, 0.75f, za[u]);
            float v = fmaf(vol, 0.97f, cur);
            int s = (__fadd_rn(v, -1.25f) >= 0.0f);
            vol = s ? 0.0f : v;
            hist = (hist << 1) | (unsigned)s;
            int tt = t + u;
            int sv = (tt >= d) ? (int)((hist >> d) & 1u) : 0;
            unsigned word = __ballot_sync(0xffffffffu, sv);
            if (lane == 0) mw[(size_t)tt * CW2] = word;
            c += sv;
        }
    }
    atomicAdd(cnt, (unsigned long long)c);
}

// ---------------- LIF scan, output layer (z ld = O3PAD, U=10) --------------
__global__ void scan_out_kernel(const float* __restrict__ z, float* __restrict__ out,
                                const int* __restrict__ delay, unsigned long long* cnt) {
    int tid = blockIdx.x * blockDim.x + threadIdx.x;
    if (tid >= BATCH * O3) return;
    int o = tid % O3;
    int b = tid / O3;
    int d = delay[o];
    const float* zp = z + (size_t)b * TSTEPS * O3PAD + o;
    float* op = out + (size_t)b * O3 * TSTEPS + (size_t)o * TSTEPS;
    float cur = 0.0f, vol = 0.0f;
    unsigned hist = 0u;
    int c = 0;
    for (int t = 0; t < TSTEPS; t += 10) {
        float za[10];
        #pragma unroll
        for (int u = 0; u < 10; u++) za[u] = zp[(size_t)(t + u) * O3PAD];
        #pragma unroll
        for (int u = 0; u < 10; u++) {
            cur = fmaf(cur, 0.75f, za[u]);
            float v = fmaf(vol, 0.97f, cur);
            int s = (__fadd_rn(v, -1.25f) >= 0.0f);
            vol = s ? 0.0f : v;
            hist = (hist << 1) | (unsigned)s;
            int tt = t + u;
            int sv = (tt >= d) ? (int)((hist >> d) & 1u) : 0;
            op[tt] = (float)sv;
            c += sv;
        }
    }
    atomicAdd(cnt, (unsigned long long)c);
}

// ---------------- finalize counts ----------------
__global__ void finalize_kernel(float* out) {
    if (threadIdx.x == 0) {
        out[96000] = __fdiv_rn((float)g_cnt[0], 4915200.0f);
        out[96001] = __fdiv_rn((float)g_cnt[1], 4915200.0f);
        out[96002] = __fdiv_rn((float)g_cnt[2], 96000.0f);
    }
}

// ---------------- launch ----------------
extern "C" void kernel_launch(void* const* d_in, const int* in_sizes, int n_in,
                              void* d_out, int out_size) {
    const float* spike = (const float*)d_in[0];
    const float* v1 = (const float*)d_in[1];
    const float* g1 = (const float*)d_in[2];
    const float* v2 = (const float*)d_in[3];
    const float* g2 = (const float*)d_in[4];
    const float* v3 = (const float*)d_in[5];
    const float* g3 = (const float*)d_in[6];
    const int*   d1 = (const int*)d_in[7];
    const int*   d2 = (const int*)d_in[8];
    const int*   d3 = (const int*)d_in[9];
    float* out = (float*)d_out;

    float *z, *W1t, *W2t, *W3t, *nrm;
    unsigned *mask1, *mask2;
    unsigned short *idx1, *idx2;
    int* cntS;
    unsigned long long* cnt;
    cudaGetSymbolAddress((void**)&z,   g_z);
    cudaGetSymbolAddress((void**)&W1t, g_W1t);
    cudaGetSymbolAddress((void**)&W2t, g_W2t);
    cudaGetSymbolAddress((void**)&W3t, g_W3t);
    cudaGetSymbolAddress((void**)&nrm, g_norm);
    cudaGetSymbolAddress((void**)&mask1, g_mask1);
    cudaGetSymbolAddress((void**)&mask2, g_mask2);
    cudaGetSymbolAddress((void**)&idx1, g_idx1);
    cudaGetSymbolAddress((void**)&idx2, g_idx2);
    cudaGetSymbolAddress((void**)&cntS, g_cntS);
    cudaGetSymbolAddress((void**)&cnt, g_cnt);

    static int smem_set = 0;
    if (!smem_set) {
        cudaFuncSetAttribute(spmm_kernel, cudaFuncAttributeMaxDynamicSharedMemorySize,
                             2 * SC * OT * (int)sizeof(float));
        smem_set = 1;
    }
    const int SPMM_SMEM = 2 * SC * OT * (int)sizeof(float);  // 126976

    init_kernel<<<64, 256>>>();

    {
        dim3 grid((TSTEPS + 31) / 32, CW1, BATCH);
        transpose_mask_kernel<<<grid, dim3(32, 8)>>>(spike);
    }

    // ---- layer 1 ----
    norm4_kernel<<<(O1 * 4) / 256, 256>>>(v1, nrm, O1, CIN);
    scale_kernel<<<dim3((CIN + 31) / 32, O1 / 32), dim3(32, 8)>>>(v1, g1, nrm, W1t, O1, CIN, O1);
    buildm_kernel<<<MROWS / 8, 256>>>(mask1, idx1, cntS, CW1, CIN, 19);
    spmm_kernel<<<dim3(MROWS / RPB, O1 / OT), 1024, SPMM_SMEM>>>(idx1, cntS, W1t, z, CIN, 19, O1, O1);
    scan512_kernel<<<(BATCH * O1) / 256, 256>>>(z, mask2, d1, cnt + 0);

    // ---- layer 2 ----
    norm4_kernel<<<(O2 * 4) / 256, 256>>>(v2, nrm, O2, O1);
    scale_kernel<<<dim3(O1 / 32, O2 / 32), dim3(32, 8)>>>(v2, g2, nrm, W2t, O2, O1, O2);
    buildm_kernel<<<MROWS / 8, 256>>>(mask2, idx2, cntS, CW2, O1, 5);
    spmm_kernel<<<dim3(MROWS / RPB, O2 / OT), 1024, SPMM_SMEM>>>(idx2, cntS, W2t, z, O1, 5, O2, O2);
    scan512_kernel<<<(BATCH * O2) / 256, 256>>>(z, mask2, d2, cnt + 1);

    // ---- layer 3 (N padded to 128) ----
    norm4_kernel<<<1, 128>>>(v3, nrm, O3, O2);
    scale_kernel<<<dim3(O2 / 32, 1), dim3(32, 8)>>>(v3, g3, nrm, W3t, O3, O2, O3PAD);
    buildm_kernel<<<MROWS / 8, 256>>>(mask2, idx2, cntS, CW2, O2, 5);
    spmm_kernel<<<dim3(MROWS / RPB, 1), 1024, SPMM_SMEM>>>(idx2, cntS, W3t, z, O2, 5, O3PAD, O3PAD);
    scan_out_kernel<<<2, 256>>>(z, out, d3, cnt + 2);

    finalize_kernel<<<1, 32>>>(out);
}

// round 13
// speedup vs baseline: 1.1780x; 1.0828x over previous
#include <cuda_runtime.h>
#include <cuda_bf16.h>
#include <math.h>
#include <stdint.h>

// Problem constants
#define BATCH 32
#define TSTEPS 300
#define CIN   2312        // 34*34*2
#define O1    512
#define O2    512
#define O3    10
#define O3PAD 128
#define MROWS (BATCH*TSTEPS)   // 9600
#define KC    248         // Eigen accumulation panel (bit-exactness anchor)
#define SC    124         // smem staging sub-panel (2 per KC panel)
#define NSMAX 19
#define CW1   73          // mask words per row, layer1
#define CW2   16          // mask words per row, layers 2/3

// ---------------- static device scratch ----------------
__device__ float g_z  [ (size_t)BATCH*TSTEPS*O1  ];
__device__ float g_W1t[ (size_t)CIN*O1 ];
__device__ float g_W2t[ (size_t)O1*O2 ];
__device__ float g_W3t[ (size_t)O2*O3PAD ];
__device__ float g_norm1[512];
__device__ float g_norm2[512];
__device__ float g_norm3[16];
__device__ unsigned g_mask1[(size_t)MROWS*CW1];
__device__ unsigned g_mask2[(size_t)MROWS*CW2];
__device__ unsigned short g_idx1[(size_t)MROWS*CIN];
__device__ unsigned short g_idx2[(size_t)MROWS*O1];
__device__ int g_cntS[(size_t)MROWS*NSMAX];
__device__ unsigned long long g_cnt[3];

// ---------------- cp.async helpers ----------------
__device__ __forceinline__ void cp_async16(uint32_t saddr, const void* gaddr) {
    asm volatile("cp.async.cg.shared.global [%0], [%1], 16;" :: "r"(saddr), "l"(gaddr));
}
__device__ __forceinline__ void cp_commit() {
    asm volatile("cp.async.commit_group;");
}
template <int N> __device__ __forceinline__ void cp_wait() {
    asm volatile("cp.async.wait_group %0;" :: "n"(N));
}
__device__ __forceinline__ uint32_t smem_u32(const void* p) {
    return (uint32_t)__cvta_generic_to_shared(p);
}

// ---------------- transpose spikes -> bitmask [B,T,CW1] --------------------
__global__ void transpose_mask_kernel(const float* __restrict__ in) {
    __shared__ float tile[32][33];
    int b  = blockIdx.z;
    int t0 = blockIdx.x * 32;
    int cw = blockIdx.y;
    int c0 = cw * 32;
    int tx = threadIdx.x, ty = threadIdx.y;   // (32,8)
    const float* inb = in + (size_t)b * CIN * TSTEPS;
    int t = t0 + tx;
    #pragma unroll
    for (int j = 0; j < 32; j += 8) {
        int c = c0 + ty + j;
        float v = 0.0f;
        if (t < TSTEPS && c < CIN) v = inb[(size_t)c * TSTEPS + t];
        tile[ty + j][tx] = v;
    }
    __syncthreads();
    #pragma unroll
    for (int j = 0; j < 32; j += 8) {
        int t2 = t0 + ty + j;
        float v = tile[tx][ty + j];
        unsigned word = __ballot_sync(0xffffffffu, v != 0.0f);
        if (tx == 0 && t2 < TSTEPS)
            g_mask1[(size_t)(b * TSTEPS + t2) * CW1 + cw] = word;
    }
}

// ---------------- norms for ALL layers + counter init ----------------------
// 4 threads per row, NEON 4-lane order per row (bit-exactness anchor).
// Rows: [0,512) layer1 (C=2312), [512,1024) layer2 (C=512), [1024,1034) layer3.
__global__ void norm_all_kernel(const float* __restrict__ v1,
                                const float* __restrict__ v2,
                                const float* __restrict__ v3) {
    int t = blockIdx.x * blockDim.x + threadIdx.x;
    if (t < 3) g_cnt[t] = 0ull;
    int j = t & 3;
    int r = t >> 2;
    const float* vr;
    int C;
    bool wr = true;
    if (r < 512) { vr = v1 + (size_t)r * CIN; C = CIN; }
    else if (r < 1024) { vr = v2 + (size_t)(r - 512) * 512; C = 512; }
    else { int o = r - 1024; if (o >= O3) { o = O3 - 1; wr = false; }
           vr = v3 + (size_t)o * 512; C = 512; }
    float s = 0.0f;
    for (int c = j; c < C; c += 4)
        s = __fadd_rn(s, __fmul_rn(vr[c], vr[c]));
    unsigned gm = 0xFu << ((((unsigned)t & 31u) >> 2) << 2);
    float u  = __shfl_down_sync(gm, s, 1, 4);
    float a  = __fadd_rn(s, u);
    float b2 = __shfl_down_sync(gm, a, 2, 4);
    if (j == 0 && wr) {
        float n = sqrtf(__fadd_rn(a, b2));
        if (r < 512) g_norm1[r] = n;
        else if (r < 1024) g_norm2[r - 512] = n;
        else g_norm3[r - 1024] = n;
    }
}

// ---------------- scale + transpose for ALL layers -------------------------
// Layer3 writes zeros into its 128-col pad (replaces init_kernel).
#define L1_TILES (73 * 16)    // 1168
#define L2_TILES (16 * 16)    // 256
#define L3_TILES (16 * 4)     // 64
__global__ __launch_bounds__(256)
void scale_all_kernel(const float* __restrict__ v1, const float* __restrict__ g1,
                      const float* __restrict__ v2, const float* __restrict__ g2,
                      const float* __restrict__ v3, const float* __restrict__ g3) {
    __shared__ float tile[32][33];
    int bid = blockIdx.x;
    const float *v, *g, *nrm;
    float* Wt;
    int O, C, ldw, cx, oy;
    if (bid < L1_TILES) {
        v = v1; g = g1; nrm = g_norm1; Wt = g_W1t; O = O1; C = CIN; ldw = O1;
        cx = bid % 73; oy = bid / 73;
    } else if (bid < L1_TILES + L2_TILES) {
        int b = bid - L1_TILES;
        v = v2; g = g2; nrm = g_norm2; Wt = g_W2t; O = O2; C = O1; ldw = O2;
        cx = b % 16; oy = b / 16;
    } else {
        int b = bid - L1_TILES - L2_TILES;
        v = v3; g = g3; nrm = g_norm3; Wt = g_W3t; O = O3; C = O2; ldw = O3PAD;
        cx = b % 16; oy = b / 16;
    }
    int c0 = cx * 32, o0 = oy * 32;
    int tx = threadIdx.x, ty = threadIdx.y;   // (32,8)
    #pragma unroll
    for (int jj = 0; jj < 32; jj += 8) {
        int o = o0 + ty + jj, c = c0 + tx;
        float val = 0.0f;
        if (o < O && c < C)
            val = __fdiv_rn(__fmul_rn(g[o], v[(size_t)o * C + c]), nrm[o]);
        tile[ty + jj][tx] = val;
    }
    __syncthreads();
    #pragma unroll
    for (int jj = 0; jj < 32; jj += 8) {
        int c = c0 + ty + jj, o = o0 + tx;
        if (c < C)
            Wt[(size_t)c * ldw + o] = tile[tx][ty + jj];
    }
}

// ---------------- build idx (byte offsets) + subchunk counts ---------------
#define OTB 512     // OT * 4 bytes
__global__ void buildm_kernel(const unsigned* __restrict__ mask,
                              unsigned short* __restrict__ idx,
                              int* __restrict__ cntS, int NW, int K, int NS) {
    __shared__ unsigned sw[8][80];
    int warp = threadIdx.x >> 5, lane = threadIdx.x & 31;
    int row = blockIdx.x * 8 + warp;
    const unsigned* mr = mask + (size_t)row * NW;
    for (int w = lane; w < NW; w += 32) sw[warp][w] = mr[w];
    __syncwarp();

    unsigned short* ir = idx + (size_t)row * K;
    int pos = 0;
    int ngroups = (NW + 31) >> 5;
    for (int g = 0; g < ngroups; g++) {
        int w = g * 32 + lane;
        unsigned word = (w < NW) ? sw[warp][w] : 0u;
        int pc = __popc(word);
        int scan = pc;
        #pragma unroll
        for (int off = 1; off < 32; off <<= 1) {
            int n = __shfl_up_sync(0xffffffffu, scan, off);
            if (lane >= off) scan += n;
        }
        int base = pos + (scan - pc);
        unsigned ww = word;
        int r = 0;
        while (ww) {
            int bit = __ffs(ww) - 1;
            int c = 32 * w + bit;
            int sub = c / SC;
            ir[base + r] = (unsigned short)((c - sub * SC) * OTB);
            r++;
            ww &= ww - 1u;
        }
        pos += __shfl_sync(0xffffffffu, scan, 31);
    }
    if (lane < NS) {
        int start = lane * SC;
        int end = start + SC; if (end > K) end = K;
        int wlo = start >> 5, whi = (end - 1) >> 5;
        int cnt = 0;
        for (int w = wlo; w <= whi; w++) {
            unsigned m = sw[warp][w];
            int cbase = w << 5;
            if (cbase < start) m &= ~((1u << (start - cbase)) - 1u);
            int rem = end - cbase;
            if (rem < 32) m &= (1u << rem) - 1u;
            cnt += __popc(m);
        }
        cntS[row * NSMAX + lane] = cnt;
    }
}

// ---------------- sparse accumulate: 1024 thr, cp.async double buffer ------
// Bit-exact: per KC panel an ascending-c fadd chain (2 SC stages, fold after
// odd/final stage), panels folded by fadd.
#define OT  128
#define RPB 128
#define RPW 4       // 32 warps x 4 rows

extern __shared__ float Ws[];   // 2 x [SC][OT] floats, then int cs[RPB*NS]

__global__ __launch_bounds__(1024)
void spmm_kernel(const unsigned short* __restrict__ idx, const int* __restrict__ cntS,
                 const float* __restrict__ W, float* __restrict__ Z,
                 int K, int NS, int ldw, int ldc) {
    const int tid  = threadIdx.x;
    const int lane = tid & 31;
    const int warp = tid >> 5;
    const int row0b = blockIdx.x * RPB;
    const int row0 = row0b + warp * RPW;
    const int o0   = blockIdx.y * OT;
    const int ocol = lane * 4;
    const uint32_t sbase = smem_u32(Ws);
    int* cs = (int*)(Ws + 2 * SC * OT);

    // cooperative load of per-row subchunk counts
    for (int i = tid; i < RPB * NS; i += 1024)
        cs[i] = cntS[(size_t)(row0b + i / NS) * NSMAX + (i % NS)];

    float4 acc[RPW], accP[RPW];
    int pos[RPW];
    #pragma unroll
    for (int j = 0; j < RPW; j++) {
        acc[j] = make_float4(0.f,0.f,0.f,0.f);
        accP[j] = make_float4(0.f,0.f,0.f,0.f);
        pos[j] = 0;
    }

    {
        int slen = (K < SC) ? K : SC;
        for (int i4 = tid; i4 < slen * (OT / 4); i4 += 1024) {
            int r = i4 >> 5, c4 = (i4 & 31) << 2;
            cp_async16(sbase + (uint32_t)(r * OT + c4) * 4u,
                       W + (size_t)r * ldw + o0 + c4);
        }
        cp_commit();
    }

    int buf = 0;
    for (int s = 0; s < NS; s++) {
        if (s + 1 < NS) {
            int ss = (s + 1) * SC;
            int slen = K - ss; if (slen > SC) slen = SC;
            uint32_t bofs = (uint32_t)((buf ^ 1) * SC * OT) * 4u;
            for (int i4 = tid; i4 < slen * (OT / 4); i4 += 1024) {
                int r = i4 >> 5, c4 = (i4 & 31) << 2;
                cp_async16(sbase + bofs + (uint32_t)(r * OT + c4) * 4u,
                           W + (size_t)(ss + r) * ldw + o0 + c4);
            }
            cp_commit();
            cp_wait<1>();
        } else {
            cp_wait<0>();
        }
        __syncthreads();

        const char* wb = (const char*)(Ws + buf * SC * OT) + ocol * 4;
        #pragma unroll
        for (int j = 0; j < RPW; j++) {
            const int row = row0 + j;
            const int cnt = cs[(warp * RPW + j) * NS + s];
            const unsigned short* ip = idx + (size_t)row * K + pos[j];
            float4 a = accP[j];
            int i = 0;
            for (; i + 4 <= cnt; i += 4) {
                float4 w0 = *(const float4*)(wb + ip[i + 0]);
                float4 w1 = *(const float4*)(wb + ip[i + 1]);
                float4 w2 = *(const float4*)(wb + ip[i + 2]);
                float4 w3 = *(const float4*)(wb + ip[i + 3]);
                a.x = __fadd_rn(a.x, w0.x); a.y = __fadd_rn(a.y, w0.y);
                a.z = __fadd_rn(a.z, w0.z); a.w = __fadd_rn(a.w, w0.w);
                a.x = __fadd_rn(a.x, w1.x); a.y = __fadd_rn(a.y, w1.y);
                a.z = __fadd_rn(a.z, w1.z); a.w = __fadd_rn(a.w, w1.w);
                a.x = __fadd_rn(a.x, w2.x); a.y = __fadd_rn(a.y, w2.y);
                a.z = __fadd_rn(a.z, w2.z); a.w = __fadd_rn(a.w, w2.w);
                a.x = __fadd_rn(a.x, w3.x); a.y = __fadd_rn(a.y, w3.y);
                a.z = __fadd_rn(a.z, w3.z); a.w = __fadd_rn(a.w, w3.w);
            }
            for (; i < cnt; i++) {
                float4 wv = *(const float4*)(wb + ip[i]);
                a.x = __fadd_rn(a.x, wv.x); a.y = __fadd_rn(a.y, wv.y);
                a.z = __fadd_rn(a.z, wv.z); a.w = __fadd_rn(a.w, wv.w);
            }
            accP[j] = a;
            pos[j] += cnt;
        }
        __syncthreads();

        if ((s & 1) == 1 || s == NS - 1) {
            #pragma unroll
            for (int j = 0; j < RPW; j++) {
                acc[j].x = __fadd_rn(acc[j].x, accP[j].x);
                acc[j].y = __fadd_rn(acc[j].y, accP[j].y);
                acc[j].z = __fadd_rn(acc[j].z, accP[j].z);
                acc[j].w = __fadd_rn(acc[j].w, accP[j].w);
                accP[j] = make_float4(0.f,0.f,0.f,0.f);
            }
        }
        buf ^= 1;
    }
    #pragma unroll
    for (int j = 0; j < RPW; j++)
        *(float4*)(Z + (size_t)(row0 + j) * ldc + o0 + ocol) = acc[j];
}

// ---------------- LIF scan, 512-wide: emits next-layer bitmask (U=10) ------
__global__ void scan512_kernel(const float* __restrict__ z, unsigned* __restrict__ maskN,
                               const int* __restrict__ delay, unsigned long long* cnt) {
    int tid = blockIdx.x * blockDim.x + threadIdx.x;  // 16384
    int o = tid & 511;
    int b = tid >> 9;
    int lane = tid & 31;
    int d = delay[o];
    const float* zp = z + (size_t)b * TSTEPS * 512 + o;
    unsigned* mw = maskN + (size_t)b * TSTEPS * CW2 + (o >> 5);
    float cur = 0.0f, vol = 0.0f;
    unsigned hist = 0u;
    int c = 0;
    for (int t = 0; t < TSTEPS; t += 10) {
        float za[10];
        #pragma unroll
        for (int u = 0; u < 10; u++) za[u] = zp[(size_t)(t + u) * 512];
        #pragma unroll
        for (int u = 0; u < 10; u++) {
            cur = fmaf(cur, 0.75f, za[u]);
            float v = fmaf(vol, 0.97f, cur);
            int s = (__fadd_rn(v, -1.25f) >= 0.0f);
            vol = s ? 0.0f : v;
            hist = (hist << 1) | (unsigned)s;
            int tt = t + u;
            int sv = (tt >= d) ? (int)((hist >> d) & 1u) : 0;
            unsigned word = __ballot_sync(0xffffffffu, sv);
            if (lane == 0) mw[(size_t)tt * CW2] = word;
            c += sv;
        }
    }
    atomicAdd(cnt, (unsigned long long)c);
}

// ---------------- LIF scan, output layer + finalize (single block) ---------
__global__ void scan_out_fin_kernel(const float* __restrict__ z, float* __restrict__ out,
                                    const int* __restrict__ delay,
                                    unsigned long long* cnt) {
    int tid = threadIdx.x;   // 320 threads
    int o = tid % O3;
    int b = tid / O3;
    int d = delay[o];
    const float* zp = z + (size_t)b * TSTEPS * O3PAD + o;
    float* op = out + (size_t)b * O3 * TSTEPS + (size_t)o * TSTEPS;
    float cur = 0.0f, vol = 0.0f;
    unsigned hist = 0u;
    int c = 0;
    for (int t = 0; t < TSTEPS; t += 10) {
        float za[10];
        #pragma unroll
        for (int u = 0; u < 10; u++) za[u] = zp[(size_t)(t + u) * O3PAD];
        #pragma unroll
        for (int u = 0; u < 10; u++) {
            cur = fmaf(cur, 0.75f, za[u]);
            float v = fmaf(vol, 0.97f, cur);
            int s = (__fadd_rn(v, -1.25f) >= 0.0f);
            vol = s ? 0.0f : v;
            hist = (hist << 1) | (unsigned)s;
            int tt = t + u;
            int sv = (tt >= d) ? (int)((hist >> d) & 1u) : 0;
            op[tt] = (float)sv;
            c += sv;
        }
    }
    atomicAdd(cnt + 2, (unsigned long long)c);
    __syncthreads();
    if (tid == 0) {
        out[96000] = __fdiv_rn((float)cnt[0], 4915200.0f);
        out[96001] = __fdiv_rn((float)cnt[1], 4915200.0f);
        out[96002] = __fdiv_rn((float)cnt[2], 96000.0f);
    }
}

// ---------------- launch ----------------
extern "C" void kernel_launch(void* const* d_in, const int* in_sizes, int n_in,
                              void* d_out, int out_size) {
    const float* spike = (const float*)d_in[0];
    const float* v1 = (const float*)d_in[1];
    const float* g1 = (const float*)d_in[2];
    const float* v2 = (const float*)d_in[3];
    const float* g2 = (const float*)d_in[4];
    const float* v3 = (const float*)d_in[5];
    const float* g3 = (const float*)d_in[6];
    const int*   d1 = (const int*)d_in[7];
    const int*   d2 = (const int*)d_in[8];
    const int*   d3 = (const int*)d_in[9];
    float* out = (float*)d_out;

    float *z, *W1t, *W2t, *W3t;
    unsigned *mask1, *mask2;
    unsigned short *idx1, *idx2;
    int* cntS;
    unsigned long long* cnt;
    cudaGetSymbolAddress((void**)&z,   g_z);
    cudaGetSymbolAddress((void**)&W1t, g_W1t);
    cudaGetSymbolAddress((void**)&W2t, g_W2t);
    cudaGetSymbolAddress((void**)&W3t, g_W3t);
    cudaGetSymbolAddress((void**)&mask1, g_mask1);
    cudaGetSymbolAddress((void**)&mask2, g_mask2);
    cudaGetSymbolAddress((void**)&idx1, g_idx1);
    cudaGetSymbolAddress((void**)&idx2, g_idx2);
    cudaGetSymbolAddress((void**)&cntS, g_cntS);
    cudaGetSymbolAddress((void**)&cnt, g_cnt);

    static cudaStream_t s2 = nullptr;
    static cudaEvent_t evA = nullptr, evB = nullptr;
    if (!s2) {
        cudaStreamCreateWithFlags(&s2, cudaStreamNonBlocking);
        cudaEventCreateWithFlags(&evA, cudaEventDisableTiming);
        cudaEventCreateWithFlags(&evB, cudaEventDisableTiming);
        cudaFuncSetAttribute(spmm_kernel, cudaFuncAttributeMaxDynamicSharedMemorySize,
                             2 * SC * OT * (int)sizeof(float) + RPB * NSMAX * (int)sizeof(int));
    }
    const int SMEM1 = 2 * SC * OT * (int)sizeof(float) + RPB * 19 * (int)sizeof(int);
    const int SMEM2 = 2 * SC * OT * (int)sizeof(float) + RPB * 5 * (int)sizeof(int);

    // ---- fork: weight prep for ALL layers on side stream ----
    cudaEventRecord(evA, 0);
    cudaStreamWaitEvent(s2, evA, 0);
    norm_all_kernel<<<17, 256, 0, s2>>>(v1, v2, v3);
    scale_all_kernel<<<L1_TILES + L2_TILES + L3_TILES, dim3(32, 8), 0, s2>>>(
        v1, g1, v2, g2, v3, g3);
    cudaEventRecord(evB, s2);

    // ---- main stream: spike transpose + layer-1 index build ----
    {
        dim3 grid((TSTEPS + 31) / 32, CW1, BATCH);
        transpose_mask_kernel<<<grid, dim3(32, 8)>>>(spike);
    }
    buildm_kernel<<<MROWS / 8, 256>>>(mask1, idx1, cntS, CW1, CIN, 19);

    // ---- join, then layer pipeline ----
    cudaStreamWaitEvent(0, evB, 0);
    spmm_kernel<<<dim3(MROWS / RPB, O1 / OT), 1024, SMEM1>>>(idx1, cntS, W1t, z, CIN, 19, O1, O1);
    scan512_kernel<<<(BATCH * O1) / 256, 256>>>(z, mask2, d1, cnt + 0);

    buildm_kernel<<<MROWS / 8, 256>>>(mask2, idx2, cntS, CW2, O1, 5);
    spmm_kernel<<<dim3(MROWS / RPB, O2 / OT), 1024, SMEM2>>>(idx2, cntS, W2t, z, O1, 5, O2, O2);
    scan512_kernel<<<(BATCH * O2) / 256, 256>>>(z, mask2, d2, cnt + 1);

    buildm_kernel<<<MROWS / 8, 256>>>(mask2, idx2, cntS, CW2, O2, 5);
    spmm_kernel<<<dim3(MROWS / RPB, 1), 1024, SMEM2>>>(idx2, cntS, W3t, z, O2, 5, O3PAD, O3PAD);
    scan_out_fin_kernel<<<1, 320>>>(z, out, d3, cnt);
}